// round 16
// baseline (speedup 1.0000x reference)
#include <cuda_runtime.h>
#include <cuda_fp16.h>
#include <cstdint>
#include <math.h>

#define B_  512
#define Z_  64
#define H_  256
#define T_  64
#define P_  10000
#define G3_ 768
#define BT_ (B_*T_)
#define PPAD 10112   // 79*128
#define KL_ 256      // both GEMMs: plain fp16, K=256

// ---------------- scratch (no allocations allowed) ----------------
__device__ float g_h0[B_*H_];
__device__ float g_gx0[G3_];
__device__ __half g_WTh0[H_*G3_];   // scan weights transposed fp16: WT[k][gate]
__device__ __half g_WTh1[H_*G3_];
__device__ float g_y0[BT_*H_];
__device__ float g_gx1[(size_t)BT_*G3_];
__device__ __align__(256) __half g_A2y0[(size_t)BT_*KL_];
__device__ __align__(256) __half g_A2out[(size_t)BT_*KL_];
__device__ __align__(256) __half g_Wb2[(size_t)PPAD*KL_];
__device__ __align__(256) __half g_Wih1b2[(size_t)G3_*KL_];

__device__ __forceinline__ float elu1(float x) {
    return x > 0.f ? x : (__expf(x) - 1.f);
}

__device__ __forceinline__ uint32_t smem_u32(const void* p) {
    uint32_t a;
    asm("{ .reg .u64 t; cvta.to.shared.u64 t, %1; cvt.u32.u64 %0, t; }" : "=r"(a) : "l"(p));
    return a;
}
__device__ __forceinline__ void cp16(uint32_t s, const void* g) {
    asm volatile("cp.async.cg.shared.global [%0], [%1], 16;" :: "r"(s), "l"(g));
}
__device__ __forceinline__ void ldsm4(uint32_t& a0, uint32_t& a1, uint32_t& a2, uint32_t& a3,
                                      uint32_t addr) {
    asm volatile("ldmatrix.sync.aligned.m8n8.x4.shared.b16 {%0,%1,%2,%3}, [%4];"
        : "=r"(a0), "=r"(a1), "=r"(a2), "=r"(a3) : "r"(addr));
}
__device__ __forceinline__ void mma16816(float* d, uint32_t a0, uint32_t a1, uint32_t a2,
                                         uint32_t a3, uint32_t b0, uint32_t b1) {
    asm volatile("mma.sync.aligned.m16n8k16.row.col.f32.f16.f16.f32 "
        "{%0,%1,%2,%3}, {%4,%5,%6,%7}, {%8,%9}, {%0,%1,%2,%3};"
        : "+f"(d[0]), "+f"(d[1]), "+f"(d[2]), "+f"(d[3])
        : "r"(a0), "r"(a1), "r"(a2), "r"(a3), "r"(b0), "r"(b1));
}

// ================= fp16 tensor GEMM: C[M,ldc] = A2[M,kdim] @ B2[N,kdim]^T + bias
// 128x128 CTA tile, 8 warps (4m x 2n), warp tile 32x64, K chunks of 64.
// 3-stage cp.async pipeline, 96 KB SMEM -> occupancy 2 (R15-proven).
#define ST_B 32768
#define GSM  (3 * ST_B)
__global__ __launch_bounds__(256, 2) void gemm_mma(
        const __half* __restrict__ A2, const __half* __restrict__ B2,
        const float* __restrict__ bias, float* __restrict__ C, int N, int ldc, int kdim) {
    extern __shared__ char sm[];
    const uint32_t sbase = smem_u32(sm);
    const int tid = threadIdx.x, lane = tid & 31, wid = tid >> 5;
    const int m0t = blockIdx.y << 7, n0t = blockIdx.x << 7;
    const int nch = kdim >> 6;

    const int lrow = tid >> 1;
    const int lkb  = (tid & 1) * 4;
    uint32_t lsoff[4];
#pragma unroll
    for (int j = 0; j < 4; ++j)
        lsoff[j] = lrow * 128 + ((((lkb + j) << 4)) ^ ((lrow & 7) << 4));
    const char* gAr = (const char*)A2 + (size_t)(m0t + lrow) * (kdim * 2) + lkb * 16;
    const char* gBr = (const char*)B2 + (size_t)(n0t + lrow) * (kdim * 2) + lkb * 16;

    const int g = lane >> 3, r = lane & 7;
    const uint32_t rx = r << 4;
    const uint32_t aKbx = (g >> 1) << 4;
    const uint32_t bKbx = (g & 1) << 4;
    uint32_t aRowOff[2], bRowOff[4];
#pragma unroll
    for (int fm = 0; fm < 2; ++fm)
        aRowOff[fm] = (uint32_t)(((wid & 3) * 32 + ((g & 1) << 3) + r + fm * 16) * 128);
#pragma unroll
    for (int p = 0; p < 4; ++p)
        bRowOff[p] = (uint32_t)(16384 + ((wid >> 2) * 64 + ((g >> 1) << 3) + r + p * 16) * 128);

    float acc[2][8][4];
#pragma unroll
    for (int i = 0; i < 2; ++i)
#pragma unroll
        for (int j = 0; j < 8; ++j)
#pragma unroll
            for (int k = 0; k < 4; ++k) acc[i][j][k] = 0.f;

#pragma unroll
    for (int c = 0; c < 2; ++c) {
        const uint32_t sa = sbase + c * ST_B;
#pragma unroll
        for (int j = 0; j < 4; ++j) {
            cp16(sa + lsoff[j], gAr + c * 128 + j * 16);
            cp16(sa + 16384 + lsoff[j], gBr + c * 128 + j * 16);
        }
        asm volatile("cp.async.commit_group;");
    }

    int stage = 0, nstage = 2;
    for (int c = 0; c < nch; ++c) {
        if (c < nch - 1) asm volatile("cp.async.wait_group 1;");
        else             asm volatile("cp.async.wait_group 0;");
        __syncthreads();

        if (c + 2 < nch) {
            const uint32_t sa = sbase + nstage * ST_B;
#pragma unroll
            for (int j = 0; j < 4; ++j) {
                cp16(sa + lsoff[j], gAr + (c + 2) * 128 + j * 16);
                cp16(sa + 16384 + lsoff[j], gBr + (c + 2) * 128 + j * 16);
            }
            asm volatile("cp.async.commit_group;");
        }

        const uint32_t sB = sbase + stage * ST_B;
#pragma unroll
        for (int kk = 0; kk < 4; ++kk) {
            const uint32_t akoff = ((uint32_t)(kk * 32) + aKbx) ^ rx;
            const uint32_t bkoff = ((uint32_t)(kk * 32) + bKbx) ^ rx;
            uint32_t a[2][4], bb[4][4];
#pragma unroll
            for (int fm = 0; fm < 2; ++fm)
                ldsm4(a[fm][0], a[fm][1], a[fm][2], a[fm][3], sB + aRowOff[fm] + akoff);
#pragma unroll
            for (int p = 0; p < 4; ++p)
                ldsm4(bb[p][0], bb[p][1], bb[p][2], bb[p][3], sB + bRowOff[p] + bkoff);
#pragma unroll
            for (int fm = 0; fm < 2; ++fm)
#pragma unroll
                for (int p = 0; p < 4; ++p) {
                    mma16816(acc[fm][2 * p],     a[fm][0], a[fm][1], a[fm][2], a[fm][3],
                             bb[p][0], bb[p][1]);
                    mma16816(acc[fm][2 * p + 1], a[fm][0], a[fm][1], a[fm][2], a[fm][3],
                             bb[p][2], bb[p][3]);
                }
        }
        stage  = (stage  == 2) ? 0 : stage  + 1;
        nstage = (nstage == 2) ? 0 : nstage + 1;
    }

#pragma unroll
    for (int fm = 0; fm < 2; ++fm) {
        const int mrow = m0t + (wid & 3) * 32 + fm * 16 + (lane >> 2);
        float* c0 = C + (size_t)mrow * ldc;
        float* c1 = C + (size_t)(mrow + 8) * ldc;
#pragma unroll
        for (int bn = 0; bn < 8; ++bn) {
            const int n = n0t + (wid >> 2) * 64 + bn * 8 + (lane & 3) * 2;
            if (n < N) {
                const float bv0 = bias[n], bv1 = bias[n + 1];
                *(float2*)(c0 + n) = make_float2(acc[fm][bn][0] + bv0, acc[fm][bn][1] + bv1);
                *(float2*)(c1 + n) = make_float2(acc[fm][bn][2] + bv0, acc[fm][bn][3] + bv1);
            }
        }
    }
}

// ---------------- fused prep: all independent weight/init transforms ----------------
// blocks: [0,768) WTh0 | [768,1536) WTh1 | [1536,2304) Wih1->fp16 |
//         [2304,2304+PPAD) Wout->fp16 | next 512 h0 | last 3 gx0
__global__ void k_prep(const float* __restrict__ z, const float* __restrict__ W_init,
                       const float* __restrict__ b_init, const float* __restrict__ emb,
                       const float* __restrict__ Wih0, const float* __restrict__ bih0,
                       const float* __restrict__ Whh0, const float* __restrict__ Whh1,
                       const float* __restrict__ Wih1, const float* __restrict__ Wout) {
    int blk = blockIdx.x;
    if (blk < 768) {
        int idx = blk * 256 + threadIdx.x;
        int k = idx / G3_, gg = idx - k * G3_;
        g_WTh0[idx] = __float2half(Whh0[gg * H_ + k]);
        return;
    }
    blk -= 768;
    if (blk < 768) {
        int idx = blk * 256 + threadIdx.x;
        int k = idx / G3_, gg = idx - k * G3_;
        g_WTh1[idx] = __float2half(Whh1[gg * H_ + k]);
        return;
    }
    blk -= 768;
    if (blk < 768) {
        int idx = blk * 256 + threadIdx.x;
        int row = idx >> 8, col = idx & 255;
        g_Wih1b2[(size_t)row * KL_ + col] = __float2half(Wih1[row * 256 + col]);
        return;
    }
    blk -= 768;
    if (blk < PPAD) {
        int idx = blk * 256 + threadIdx.x;
        int row = idx >> 8, col = idx & 255;
        float x = (row < P_) ? Wout[row * 256 + col] : 0.f;
        g_Wb2[(size_t)row * KL_ + col] = __float2half(x);
        return;
    }
    blk -= PPAD;
    if (blk < 512) {
        int idx = blk * 256 + threadIdx.x;
        int b = idx >> 8, h = idx & 255;
        float s = b_init[h];
        const float* zr = z + b * Z_;
        const float* wr = W_init + h * Z_;
#pragma unroll 16
        for (int i = 0; i < Z_; i++) s += zr[i] * wr[i];
        g_h0[idx] = elu1(s);
        return;
    }
    blk -= 512;
    {
        int gg = blk * 256 + threadIdx.x;
        float s = bih0[gg];
        const float* wr = Wih0 + gg * H_;
#pragma unroll 8
        for (int i = 0; i < H_; i++) s += emb[i] * wr[i];
        g_gx0[gg] = s;
    }
}
#define PREP_BLOCKS (768*3 + PPAD + 512 + 3)

// ---------------- GRU scan: 384 threads, BB=4, fp16 weights (half2 per k) ----------------
#define BB 4
__global__ __launch_bounds__(384) void gru_scan(
        const __half* __restrict__ WTh, const float* __restrict__ bhh,
        const float* __restrict__ gx, int gx_per_bt,
        float* __restrict__ y, int out_mode) {   // 0: plain fp16 -> g_A2y0 ; 1: fp32 -> y
    __shared__ __align__(16) float h_s [BB][H_];
    __shared__ __align__(16) float gh_s[BB][G3_];
    __shared__ __align__(16) float gx_s[BB][G3_];
    int tid = threadIdx.x;
    int b0 = blockIdx.x * BB;

    for (int i = tid; i < BB * H_; i += 384) h_s[i >> 8][i & 255] = g_h0[b0 * H_ + i];
    if (!gx_per_bt) {
        for (int i = tid; i < G3_; i += 384) gx_s[0][i] = gx[i];
    }
    float2 bias2 = *(const float2*)(bhh + tid * 2);
    __syncthreads();

    for (int step = 0; step < T_; step++) {
        if (gx_per_bt) {
#pragma unroll
            for (int i = 0; i < 2; ++i) {
                int idx = tid + i * 384;
                int rr = idx / 192;
                int c4 = (idx - rr * 192) * 4;
                *(float4*)&gx_s[rr][c4] =
                    *(const float4*)&gx[((size_t)(b0 + rr) * T_ + step) * G3_ + c4];
            }
        }
        float acc[BB][2];
#pragma unroll
        for (int rr = 0; rr < BB; rr++) { acc[rr][0] = 0.f; acc[rr][1] = 0.f; }
        {
            const __half* wp = WTh + tid * 2;
#pragma unroll 8
            for (int k = 0; k < H_; k += 4) {
                float2 w0 = __half22float2(*(const __half2*)(wp + (size_t)(k+0) * G3_));
                float2 w1 = __half22float2(*(const __half2*)(wp + (size_t)(k+1) * G3_));
                float2 w2 = __half22float2(*(const __half2*)(wp + (size_t)(k+2) * G3_));
                float2 w3 = __half22float2(*(const __half2*)(wp + (size_t)(k+3) * G3_));
#pragma unroll
                for (int rr = 0; rr < BB; rr++) {
                    float4 hv = *(const float4*)&h_s[rr][k];
                    acc[rr][0] += hv.x*w0.x + hv.y*w1.x + hv.z*w2.x + hv.w*w3.x;
                    acc[rr][1] += hv.x*w0.y + hv.y*w1.y + hv.z*w2.y + hv.w*w3.y;
                }
            }
#pragma unroll
            for (int rr = 0; rr < BB; rr++) {
                float2 gv = make_float2(acc[rr][0] + bias2.x, acc[rr][1] + bias2.y);
                *(float2*)&gh_s[rr][tid * 2] = gv;
            }
        }
        __syncthreads();
        if (tid < H_) {
#pragma unroll
            for (int rr = 0; rr < BB; rr++) {
                int gr = gx_per_bt ? rr : 0;
                float xr = gx_s[gr][tid], xz = gx_s[gr][H_+tid], xn = gx_s[gr][2*H_+tid];
                float hr = gh_s[rr][tid], hz = gh_s[rr][H_+tid], hn = gh_s[rr][2*H_+tid];
                float rg = 1.f / (1.f + __expf(-(xr + hr)));
                float ug = 1.f / (1.f + __expf(-(xz + hz)));
                float ng = tanhf(xn + rg * hn);
                float hold = h_s[rr][tid];
                float hnew = (1.f - ug) * ng + ug * hold;
                h_s[rr][tid] = hnew;
                size_t row = (size_t)(b0 + rr) * T_ + step;
                if (out_mode == 0) g_A2y0[row * KL_ + tid] = __float2half(hnew);
                else               y[row * H_ + tid] = hnew;
            }
        }
        __syncthreads();
    }
}

// ---------------- LayerNorm + ELU -> plain fp16 ----------------
__global__ void k_ln_elu(const float* __restrict__ y, const float* __restrict__ lng,
                         const float* __restrict__ lnb) {
    int warp = threadIdx.x >> 5, lane = threadIdx.x & 31;
    int row = blockIdx.x * 8 + warp;
    const float* p = y + (size_t)row * H_;
    float v[8], s = 0.f, sq = 0.f;
#pragma unroll
    for (int i = 0; i < 8; i++) { v[i] = p[lane + 32*i]; s += v[i]; sq += v[i]*v[i]; }
#pragma unroll
    for (int o = 16; o; o >>= 1) {
        s  += __shfl_xor_sync(0xffffffffu, s,  o);
        sq += __shfl_xor_sync(0xffffffffu, sq, o);
    }
    float mu  = s  * (1.f / H_);
    float var = sq * (1.f / H_) - mu * mu;
    float inv = rsqrtf(var + 1e-5f);
#pragma unroll
    for (int i = 0; i < 8; i++) {
        int c = lane + 32*i;
        float t = elu1((v[i] - mu) * inv * lng[c] + lnb[c]);
        g_A2out[(size_t)row * KL_ + c] = __float2half(t);
    }
}

// ---------------- launch ----------------
extern "C" void kernel_launch(void* const* d_in, const int* in_sizes, int n_in,
                              void* d_out, int out_size) {
    const float* z      = (const float*)d_in[0];
    const float* W_init = (const float*)d_in[1];
    const float* b_init = (const float*)d_in[2];
    const float* emb    = (const float*)d_in[3];
    const float* W_ih0  = (const float*)d_in[4];
    const float* W_hh0  = (const float*)d_in[5];
    const float* b_ih0  = (const float*)d_in[6];
    const float* b_hh0  = (const float*)d_in[7];
    const float* W_ih1  = (const float*)d_in[8];
    const float* W_hh1  = (const float*)d_in[9];
    const float* b_ih1  = (const float*)d_in[10];
    const float* b_hh1  = (const float*)d_in[11];
    const float* ln_g   = (const float*)d_in[12];
    const float* ln_b   = (const float*)d_in[13];
    const float* W_out  = (const float*)d_in[14];
    const float* b_out  = (const float*)d_in[15];

    float *p_y0, *p_gx0, *p_gx1;
    __half *p_WTh0, *p_WTh1, *p_A2y0, *p_A2out, *p_Wb2, *p_Wih1b2;
    cudaGetSymbolAddress((void**)&p_WTh0, g_WTh0);
    cudaGetSymbolAddress((void**)&p_WTh1, g_WTh1);
    cudaGetSymbolAddress((void**)&p_y0,  g_y0);
    cudaGetSymbolAddress((void**)&p_gx0, g_gx0);
    cudaGetSymbolAddress((void**)&p_gx1, g_gx1);
    cudaGetSymbolAddress((void**)&p_A2y0, g_A2y0);
    cudaGetSymbolAddress((void**)&p_A2out, g_A2out);
    cudaGetSymbolAddress((void**)&p_Wb2, g_Wb2);
    cudaGetSymbolAddress((void**)&p_Wih1b2, g_Wih1b2);

    cudaFuncSetAttribute(gemm_mma, cudaFuncAttributeMaxDynamicSharedMemorySize, GSM);

    // 0: fused prep (all independent transforms concurrently)
    k_prep<<<PREP_BLOCKS, 256>>>(z, W_init, b_init, emb, W_ih0, b_ih0,
                                 W_hh0, W_hh1, W_ih1, W_out);

    // 1: layer-0 scan -> fp16 A
    gru_scan<<<B_/BB, 384>>>(p_WTh0, b_hh0, p_gx0, 0, nullptr, 0);

    // 2: gx1 = y0 @ W_ih1^T + b_ih1  (K=256, plain fp16)
    gemm_mma<<<dim3(G3_/128, BT_/128), 256, GSM>>>(p_A2y0, p_Wih1b2, b_ih1, p_gx1,
                                                   G3_, G3_, KL_);

    // 3: layer-1 scan -> fp32 y   (profiled launch)
    gru_scan<<<B_/BB, 384>>>(p_WTh1, b_hh1, p_gx1, 1, p_y0, 1);

    // 4: LayerNorm + ELU -> plain fp16 A
    k_ln_elu<<<BT_/8, 256>>>(p_y0, ln_g, ln_b);

    // 5: logits = yln @ W_out^T + b_out  (K=256, plain fp16)
    gemm_mma<<<dim3(PPAD/128, BT_/128), 256, GSM>>>(p_A2out, p_Wb2, b_out, (float*)d_out,
                                                    P_, P_, KL_);
}

// round 17
// speedup vs baseline: 1.1402x; 1.1402x over previous
#include <cuda_runtime.h>
#include <cuda_fp16.h>
#include <cstdint>
#include <math.h>

#define B_  512
#define Z_  64
#define H_  256
#define T_  64
#define P_  10000
#define G3_ 768
#define BT_ (B_*T_)
#define PPAD 10112   // 79*128
#define KL_ 256      // both GEMMs: plain fp16, K=256

// ---------------- scratch (no allocations allowed) ----------------
__device__ float g_h0[B_*H_];
__device__ float g_gx0[G3_];
__device__ __half g_WTh0[H_*G3_];   // scan weights transposed fp16: WT[k][gate]
__device__ __half g_WTh1[H_*G3_];
__device__ float g_y0[BT_*H_];
__device__ float g_gx1[(size_t)BT_*G3_];
__device__ __align__(256) __half g_A2y0[(size_t)BT_*KL_];
__device__ __align__(256) __half g_A2out[(size_t)BT_*KL_];
__device__ __align__(256) __half g_Wb2[(size_t)PPAD*KL_];
__device__ __align__(256) __half g_Wih1b2[(size_t)G3_*KL_];

__device__ __forceinline__ float elu1(float x) {
    return x > 0.f ? x : (__expf(x) - 1.f);
}

__device__ __forceinline__ uint32_t smem_u32(const void* p) {
    uint32_t a;
    asm("{ .reg .u64 t; cvta.to.shared.u64 t, %1; cvt.u32.u64 %0, t; }" : "=r"(a) : "l"(p));
    return a;
}
__device__ __forceinline__ void cp16(uint32_t s, const void* g) {
    asm volatile("cp.async.cg.shared.global [%0], [%1], 16;" :: "r"(s), "l"(g));
}
__device__ __forceinline__ void ldsm4(uint32_t& a0, uint32_t& a1, uint32_t& a2, uint32_t& a3,
                                      uint32_t addr) {
    asm volatile("ldmatrix.sync.aligned.m8n8.x4.shared.b16 {%0,%1,%2,%3}, [%4];"
        : "=r"(a0), "=r"(a1), "=r"(a2), "=r"(a3) : "r"(addr));
}
__device__ __forceinline__ void mma16816(float* d, uint32_t a0, uint32_t a1, uint32_t a2,
                                         uint32_t a3, uint32_t b0, uint32_t b1) {
    asm volatile("mma.sync.aligned.m16n8k16.row.col.f32.f16.f16.f32 "
        "{%0,%1,%2,%3}, {%4,%5,%6,%7}, {%8,%9}, {%0,%1,%2,%3};"
        : "+f"(d[0]), "+f"(d[1]), "+f"(d[2]), "+f"(d[3])
        : "r"(a0), "r"(a1), "r"(a2), "r"(a3), "r"(b0), "r"(b1));
}

// ================= fp16 tensor GEMM: C[M,ldc] = A2[M,kdim] @ B2[N,kdim]^T + bias
// 128x128 CTA tile, 8 warps (4m x 2n), warp tile 32x64, K chunks of 64.
// 3-stage cp.async pipeline, 96 KB SMEM -> occupancy 2 (R15-proven).
#define ST_B 32768
#define GSM  (3 * ST_B)
__global__ __launch_bounds__(256, 2) void gemm_mma(
        const __half* __restrict__ A2, const __half* __restrict__ B2,
        const float* __restrict__ bias, float* __restrict__ C, int N, int ldc, int kdim) {
    extern __shared__ char sm[];
    const uint32_t sbase = smem_u32(sm);
    const int tid = threadIdx.x, lane = tid & 31, wid = tid >> 5;
    const int m0t = blockIdx.y << 7, n0t = blockIdx.x << 7;
    const int nch = kdim >> 6;

    const int lrow = tid >> 1;
    const int lkb  = (tid & 1) * 4;
    uint32_t lsoff[4];
#pragma unroll
    for (int j = 0; j < 4; ++j)
        lsoff[j] = lrow * 128 + ((((lkb + j) << 4)) ^ ((lrow & 7) << 4));
    const char* gAr = (const char*)A2 + (size_t)(m0t + lrow) * (kdim * 2) + lkb * 16;
    const char* gBr = (const char*)B2 + (size_t)(n0t + lrow) * (kdim * 2) + lkb * 16;

    const int g = lane >> 3, r = lane & 7;
    const uint32_t rx = r << 4;
    const uint32_t aKbx = (g >> 1) << 4;
    const uint32_t bKbx = (g & 1) << 4;
    uint32_t aRowOff[2], bRowOff[4];
#pragma unroll
    for (int fm = 0; fm < 2; ++fm)
        aRowOff[fm] = (uint32_t)(((wid & 3) * 32 + ((g & 1) << 3) + r + fm * 16) * 128);
#pragma unroll
    for (int p = 0; p < 4; ++p)
        bRowOff[p] = (uint32_t)(16384 + ((wid >> 2) * 64 + ((g >> 1) << 3) + r + p * 16) * 128);

    float acc[2][8][4];
#pragma unroll
    for (int i = 0; i < 2; ++i)
#pragma unroll
        for (int j = 0; j < 8; ++j)
#pragma unroll
            for (int k = 0; k < 4; ++k) acc[i][j][k] = 0.f;

#pragma unroll
    for (int c = 0; c < 2; ++c) {
        const uint32_t sa = sbase + c * ST_B;
#pragma unroll
        for (int j = 0; j < 4; ++j) {
            cp16(sa + lsoff[j], gAr + c * 128 + j * 16);
            cp16(sa + 16384 + lsoff[j], gBr + c * 128 + j * 16);
        }
        asm volatile("cp.async.commit_group;");
    }

    int stage = 0, nstage = 2;
    for (int c = 0; c < nch; ++c) {
        if (c < nch - 1) asm volatile("cp.async.wait_group 1;");
        else             asm volatile("cp.async.wait_group 0;");
        __syncthreads();

        if (c + 2 < nch) {
            const uint32_t sa = sbase + nstage * ST_B;
#pragma unroll
            for (int j = 0; j < 4; ++j) {
                cp16(sa + lsoff[j], gAr + (c + 2) * 128 + j * 16);
                cp16(sa + 16384 + lsoff[j], gBr + (c + 2) * 128 + j * 16);
            }
            asm volatile("cp.async.commit_group;");
        }

        const uint32_t sB = sbase + stage * ST_B;
#pragma unroll
        for (int kk = 0; kk < 4; ++kk) {
            const uint32_t akoff = ((uint32_t)(kk * 32) + aKbx) ^ rx;
            const uint32_t bkoff = ((uint32_t)(kk * 32) + bKbx) ^ rx;
            uint32_t a[2][4], bb[4][4];
#pragma unroll
            for (int fm = 0; fm < 2; ++fm)
                ldsm4(a[fm][0], a[fm][1], a[fm][2], a[fm][3], sB + aRowOff[fm] + akoff);
#pragma unroll
            for (int p = 0; p < 4; ++p)
                ldsm4(bb[p][0], bb[p][1], bb[p][2], bb[p][3], sB + bRowOff[p] + bkoff);
#pragma unroll
            for (int fm = 0; fm < 2; ++fm)
#pragma unroll
                for (int p = 0; p < 4; ++p) {
                    mma16816(acc[fm][2 * p],     a[fm][0], a[fm][1], a[fm][2], a[fm][3],
                             bb[p][0], bb[p][1]);
                    mma16816(acc[fm][2 * p + 1], a[fm][0], a[fm][1], a[fm][2], a[fm][3],
                             bb[p][2], bb[p][3]);
                }
        }
        stage  = (stage  == 2) ? 0 : stage  + 1;
        nstage = (nstage == 2) ? 0 : nstage + 1;
    }

#pragma unroll
    for (int fm = 0; fm < 2; ++fm) {
        const int mrow = m0t + (wid & 3) * 32 + fm * 16 + (lane >> 2);
        float* c0 = C + (size_t)mrow * ldc;
        float* c1 = C + (size_t)(mrow + 8) * ldc;
#pragma unroll
        for (int bn = 0; bn < 8; ++bn) {
            const int n = n0t + (wid >> 2) * 64 + bn * 8 + (lane & 3) * 2;
            if (n < N) {
                const float bv0 = bias[n], bv1 = bias[n + 1];
                *(float2*)(c0 + n) = make_float2(acc[fm][bn][0] + bv0, acc[fm][bn][1] + bv1);
                *(float2*)(c1 + n) = make_float2(acc[fm][bn][2] + bv0, acc[fm][bn][3] + bv1);
            }
        }
    }
}

// ---------------- fused prep: all independent weight/init transforms ----------------
__global__ void k_prep(const float* __restrict__ z, const float* __restrict__ W_init,
                       const float* __restrict__ b_init, const float* __restrict__ emb,
                       const float* __restrict__ Wih0, const float* __restrict__ bih0,
                       const float* __restrict__ Whh0, const float* __restrict__ Whh1,
                       const float* __restrict__ Wih1, const float* __restrict__ Wout) {
    int blk = blockIdx.x;
    if (blk < 768) {
        int idx = blk * 256 + threadIdx.x;
        int k = idx / G3_, gg = idx - k * G3_;
        g_WTh0[idx] = __float2half(Whh0[gg * H_ + k]);
        return;
    }
    blk -= 768;
    if (blk < 768) {
        int idx = blk * 256 + threadIdx.x;
        int k = idx / G3_, gg = idx - k * G3_;
        g_WTh1[idx] = __float2half(Whh1[gg * H_ + k]);
        return;
    }
    blk -= 768;
    if (blk < 768) {
        int idx = blk * 256 + threadIdx.x;
        int row = idx >> 8, col = idx & 255;
        g_Wih1b2[(size_t)row * KL_ + col] = __float2half(Wih1[row * 256 + col]);
        return;
    }
    blk -= 768;
    if (blk < PPAD) {
        int idx = blk * 256 + threadIdx.x;
        int row = idx >> 8, col = idx & 255;
        float x = (row < P_) ? Wout[row * 256 + col] : 0.f;
        g_Wb2[(size_t)row * KL_ + col] = __float2half(x);
        return;
    }
    blk -= PPAD;
    if (blk < 512) {
        int idx = blk * 256 + threadIdx.x;
        int b = idx >> 8, h = idx & 255;
        float s = b_init[h];
        const float* zr = z + b * Z_;
        const float* wr = W_init + h * Z_;
#pragma unroll 16
        for (int i = 0; i < Z_; i++) s += zr[i] * wr[i];
        g_h0[idx] = elu1(s);
        return;
    }
    blk -= 512;
    {
        int gg = blk * 256 + threadIdx.x;
        float s = bih0[gg];
        const float* wr = Wih0 + gg * H_;
#pragma unroll 8
        for (int i = 0; i < H_; i++) s += emb[i] * wr[i];
        g_gx0[gg] = s;
    }
}
#define PREP_BLOCKS (768*3 + PPAD + 512 + 3)

// ---------------- GRU scan: 384 threads, BB=4, fp16 weights (R15 version, unroll 4) ----
#define BB 4
__global__ __launch_bounds__(384) void gru_scan(
        const __half* __restrict__ WTh, const float* __restrict__ bhh,
        const float* __restrict__ gx, int gx_per_bt,
        float* __restrict__ y, int out_mode) {   // 0: plain fp16 -> g_A2y0 ; 1: fp32 -> y
    __shared__ __align__(16) float h_s [BB][H_];
    __shared__ __align__(16) float gh_s[BB][G3_];
    __shared__ __align__(16) float gx_s[BB][G3_];
    int tid = threadIdx.x;
    int b0 = blockIdx.x * BB;

    for (int i = tid; i < BB * H_; i += 384) h_s[i >> 8][i & 255] = g_h0[b0 * H_ + i];
    if (!gx_per_bt) {
        for (int i = tid; i < G3_; i += 384) gx_s[0][i] = gx[i];
    }
    float2 bias2 = *(const float2*)(bhh + tid * 2);
    __syncthreads();

    for (int step = 0; step < T_; step++) {
        if (gx_per_bt) {
#pragma unroll
            for (int i = 0; i < 2; ++i) {
                int idx = tid + i * 384;
                int rr = idx / 192;
                int c4 = (idx - rr * 192) * 4;
                *(float4*)&gx_s[rr][c4] =
                    *(const float4*)&gx[((size_t)(b0 + rr) * T_ + step) * G3_ + c4];
            }
        }
        float acc[BB][2];
#pragma unroll
        for (int rr = 0; rr < BB; rr++) { acc[rr][0] = 0.f; acc[rr][1] = 0.f; }
        {
            const __half* wp = WTh + tid * 2;
#pragma unroll 4
            for (int k = 0; k < H_; k += 4) {
                float2 w0 = __half22float2(*(const __half2*)(wp + (size_t)(k+0) * G3_));
                float2 w1 = __half22float2(*(const __half2*)(wp + (size_t)(k+1) * G3_));
                float2 w2 = __half22float2(*(const __half2*)(wp + (size_t)(k+2) * G3_));
                float2 w3 = __half22float2(*(const __half2*)(wp + (size_t)(k+3) * G3_));
#pragma unroll
                for (int rr = 0; rr < BB; rr++) {
                    float4 hv = *(const float4*)&h_s[rr][k];
                    acc[rr][0] += hv.x*w0.x + hv.y*w1.x + hv.z*w2.x + hv.w*w3.x;
                    acc[rr][1] += hv.x*w0.y + hv.y*w1.y + hv.z*w2.y + hv.w*w3.y;
                }
            }
#pragma unroll
            for (int rr = 0; rr < BB; rr++) {
                float2 gv = make_float2(acc[rr][0] + bias2.x, acc[rr][1] + bias2.y);
                *(float2*)&gh_s[rr][tid * 2] = gv;
            }
        }
        __syncthreads();
        if (tid < H_) {
#pragma unroll
            for (int rr = 0; rr < BB; rr++) {
                int gr = gx_per_bt ? rr : 0;
                float xr = gx_s[gr][tid], xz = gx_s[gr][H_+tid], xn = gx_s[gr][2*H_+tid];
                float hr = gh_s[rr][tid], hz = gh_s[rr][H_+tid], hn = gh_s[rr][2*H_+tid];
                float rg = 1.f / (1.f + __expf(-(xr + hr)));
                float ug = 1.f / (1.f + __expf(-(xz + hz)));
                float ng = tanhf(xn + rg * hn);
                float hold = h_s[rr][tid];
                float hnew = (1.f - ug) * ng + ug * hold;
                h_s[rr][tid] = hnew;
                size_t row = (size_t)(b0 + rr) * T_ + step;
                if (out_mode == 0) g_A2y0[row * KL_ + tid] = __float2half(hnew);
                else               y[row * H_ + tid] = hnew;
            }
        }
        __syncthreads();
    }
}

// ---------------- LayerNorm + ELU -> plain fp16 ----------------
__global__ void k_ln_elu(const float* __restrict__ y, const float* __restrict__ lng,
                         const float* __restrict__ lnb) {
    int warp = threadIdx.x >> 5, lane = threadIdx.x & 31;
    int row = blockIdx.x * 8 + warp;
    const float* p = y + (size_t)row * H_;
    float v[8], s = 0.f, sq = 0.f;
#pragma unroll
    for (int i = 0; i < 8; i++) { v[i] = p[lane + 32*i]; s += v[i]; sq += v[i]*v[i]; }
#pragma unroll
    for (int o = 16; o; o >>= 1) {
        s  += __shfl_xor_sync(0xffffffffu, s,  o);
        sq += __shfl_xor_sync(0xffffffffu, sq, o);
    }
    float mu  = s  * (1.f / H_);
    float var = sq * (1.f / H_) - mu * mu;
    float inv = rsqrtf(var + 1e-5f);
#pragma unroll
    for (int i = 0; i < 8; i++) {
        int c = lane + 32*i;
        float t = elu1((v[i] - mu) * inv * lng[c] + lnb[c]);
        g_A2out[(size_t)row * KL_ + c] = __float2half(t);
    }
}

// ---------------- launch ----------------
extern "C" void kernel_launch(void* const* d_in, const int* in_sizes, int n_in,
                              void* d_out, int out_size) {
    const float* z      = (const float*)d_in[0];
    const float* W_init = (const float*)d_in[1];
    const float* b_init = (const float*)d_in[2];
    const float* emb    = (const float*)d_in[3];
    const float* W_ih0  = (const float*)d_in[4];
    const float* W_hh0  = (const float*)d_in[5];
    const float* b_ih0  = (const float*)d_in[6];
    const float* b_hh0  = (const float*)d_in[7];
    const float* W_ih1  = (const float*)d_in[8];
    const float* W_hh1  = (const float*)d_in[9];
    const float* b_ih1  = (const float*)d_in[10];
    const float* b_hh1  = (const float*)d_in[11];
    const float* ln_g   = (const float*)d_in[12];
    const float* ln_b   = (const float*)d_in[13];
    const float* W_out  = (const float*)d_in[14];
    const float* b_out  = (const float*)d_in[15];

    float *p_y0, *p_gx0, *p_gx1;
    __half *p_WTh0, *p_WTh1, *p_A2y0, *p_A2out, *p_Wb2, *p_Wih1b2;
    cudaGetSymbolAddress((void**)&p_WTh0, g_WTh0);
    cudaGetSymbolAddress((void**)&p_WTh1, g_WTh1);
    cudaGetSymbolAddress((void**)&p_y0,  g_y0);
    cudaGetSymbolAddress((void**)&p_gx0, g_gx0);
    cudaGetSymbolAddress((void**)&p_gx1, g_gx1);
    cudaGetSymbolAddress((void**)&p_A2y0, g_A2y0);
    cudaGetSymbolAddress((void**)&p_A2out, g_A2out);
    cudaGetSymbolAddress((void**)&p_Wb2, g_Wb2);
    cudaGetSymbolAddress((void**)&p_Wih1b2, g_Wih1b2);

    cudaFuncSetAttribute(gemm_mma, cudaFuncAttributeMaxDynamicSharedMemorySize, GSM);

    // 0: fused prep (all independent transforms concurrently)
    k_prep<<<PREP_BLOCKS, 256>>>(z, W_init, b_init, emb, W_ih0, b_ih0,
                                 W_hh0, W_hh1, W_ih1, W_out);

    // 1: layer-0 scan -> fp16 A
    gru_scan<<<B_/BB, 384>>>(p_WTh0, b_hh0, p_gx0, 0, nullptr, 0);

    // 2: gx1 = y0 @ W_ih1^T + b_ih1  (K=256, plain fp16)
    gemm_mma<<<dim3(G3_/128, BT_/128), 256, GSM>>>(p_A2y0, p_Wih1b2, b_ih1, p_gx1,
                                                   G3_, G3_, KL_);

    // 3: layer-1 scan -> fp32 y   (profiled launch)
    gru_scan<<<B_/BB, 384>>>(p_WTh1, b_hh1, p_gx1, 1, p_y0, 1);

    // 4: LayerNorm + ELU -> plain fp16 A
    k_ln_elu<<<BT_/8, 256>>>(p_y0, ln_g, ln_b);

    // 5: logits = yln @ W_out^T + b_out  (K=256, plain fp16)
    gemm_mma<<<dim3(PPAD/128, BT_/128), 256, GSM>>>(p_A2out, p_Wb2, b_out, (float*)d_out,
                                                    P_, P_, KL_);
}